// round 13
// baseline (speedup 1.0000x reference)
#include <cuda_runtime.h>

// Reference semantics after dead-code elimination:
//   r  = eye(3)                       (unconditional overwrite in reference)
//   tb = -mean(mkpts0, axis=1)        ( = -r @ src_mean with r = I )
// Output: 12 floats = [r row-major (9), tb (3)]; identity 1s at flat 0,4,8.
//
// TERMINAL configuration. The kernel is launch-overhead-bound: 96 KB input
// = ~4 ns of HBM time; measured kernel dur 3.84-4.35 us across the full
// shape sweep (TPB in {256,512,1024} x grid in {1,3}) is T_ovh launch ramp
// (~5000 cyc) + one memory round trip (~600 cyc) + ~100 cyc reduction tail.
// Wall dur_us is bimodal (~4.55 / ~6.9) on byte-identical sources: harness
// replay/clock state, not kernel structure.
// Best shape: grid=3 (one CTA/row spreads LDG issue across 3 SMs' LSUs),
// TPB=1024 (2 float4/thread, all loads in flight in one round trip),
// 5-shfl warp reduce + bar + LDS.128/3-FADD/3-SHFL fold.

#define ROWLEN   8192
#define TPB      1024
#define NWARPS   (TPB / 32)          // 32
#define INV_NEG  (-1.0f / 8192.0f)   // exact: power-of-two divisor

__global__ void __launch_bounds__(TPB, 1)
svdhead_kernel(const float* __restrict__ mkpts0, float* __restrict__ out) {
    const int b = blockIdx.x;       // row 0..2
    const int t = threadIdx.x;

    // Block 0 writes the 3x3 identity (1s at flat indices 0, 4, 8).
    if (b == 0 && t < 3) {
        if (t == 0) reinterpret_cast<float4*>(out)[0] = make_float4(1.f, 0.f, 0.f, 0.f);
        if (t == 1) reinterpret_cast<float4*>(out)[1] = make_float4(1.f, 0.f, 0.f, 0.f);
        if (t == 2) out[8] = 1.0f;
    }

    // 8192 floats = 2048 float4; 1024 threads -> exactly 2 float4 each,
    // both issued back-to-back (one memory round trip block-wide).
    const float4* row4 = reinterpret_cast<const float4*>(mkpts0) + (size_t)b * (ROWLEN / 4);
    float4 v0 = row4[t];
    float4 v1 = row4[t + TPB];

    float sum = ((v0.x + v0.y) + (v0.z + v0.w)) + ((v1.x + v1.y) + (v1.z + v1.w));

    // Warp tree reduce: 5 shfl.
    #pragma unroll
    for (int off = 16; off > 0; off >>= 1)
        sum += __shfl_xor_sync(0xFFFFFFFFu, sum, off);

    __shared__ float warp_sums[NWARPS];
    if ((t & 31) == 0) warp_sums[t >> 5] = sum;
    __syncthreads();

    // Final fold: lanes 0-7 each grab 4 contiguous warp sums with one
    // conflict-free LDS.128, pairwise-add, then a 3-deep shfl tree.
    if (t < 8) {
        float4 w = reinterpret_cast<const float4*>(warp_sums)[t];
        float s = (w.x + w.y) + (w.z + w.w);
        #pragma unroll
        for (int off = 4; off > 0; off >>= 1)
            s += __shfl_xor_sync(0x000000FFu, s, off);
        if (t == 0)
            out[9 + b] = s * INV_NEG;
    }
}

extern "C" void kernel_launch(void* const* d_in, const int* in_sizes, int n_in,
                              void* d_out, int out_size) {
    const float* mkpts0 = (const float*)d_in[0];
    float* out = (float*)d_out;
    svdhead_kernel<<<3, TPB>>>(mkpts0, out);
}

// round 14
// speedup vs baseline: 1.5411x; 1.5411x over previous
#include <cuda_runtime.h>

// Reference semantics after dead-code elimination:
//   r  = eye(3)                       (unconditional overwrite in reference)
//   tb = -mean(mkpts0, axis=1)        ( = -r @ src_mean with r = I )
// Output: 12 floats = [r row-major (9), tb (3)]; identity 1s at flat 0,4,8.
//
// TERMINAL configuration. Launch-overhead-bound: 96 KB input = ~4 ns of HBM
// time; kernel dur (3.84-4.48 us across 13 rounds, source-insensitive) is
// T_ovh launch ramp (~5000 cyc) + one memory round trip (~600 cyc) + ~100
// cyc reduction tail. Wall dur_us ranges 4.5-7.2 us on byte-identical
// sources (harness replay/clock draw). Shape sweep complete: TPB in
// {256,512,1024} x grid in {1,3}; this shape held the best samples.

#define ROWLEN   8192
#define TPB      1024
#define NWARPS   (TPB / 32)          // 32
#define INV_NEG  (-1.0f / 8192.0f)   // exact: power-of-two divisor

__global__ void __launch_bounds__(TPB, 1)
svdhead_kernel(const float* __restrict__ mkpts0, float* __restrict__ out) {
    const int b = blockIdx.x;       // row 0..2
    const int t = threadIdx.x;

    // Block 0 writes the 3x3 identity (1s at flat indices 0, 4, 8).
    if (b == 0 && t < 3) {
        if (t == 0) reinterpret_cast<float4*>(out)[0] = make_float4(1.f, 0.f, 0.f, 0.f);
        if (t == 1) reinterpret_cast<float4*>(out)[1] = make_float4(1.f, 0.f, 0.f, 0.f);
        if (t == 2) out[8] = 1.0f;
    }

    // 8192 floats = 2048 float4; 1024 threads -> exactly 2 float4 each,
    // both issued back-to-back (one memory round trip block-wide).
    const float4* row4 = reinterpret_cast<const float4*>(mkpts0) + (size_t)b * (ROWLEN / 4);
    float4 v0 = row4[t];
    float4 v1 = row4[t + TPB];

    float sum = ((v0.x + v0.y) + (v0.z + v0.w)) + ((v1.x + v1.y) + (v1.z + v1.w));

    // Warp tree reduce: 5 shfl.
    #pragma unroll
    for (int off = 16; off > 0; off >>= 1)
        sum += __shfl_xor_sync(0xFFFFFFFFu, sum, off);

    __shared__ float warp_sums[NWARPS];
    if ((t & 31) == 0) warp_sums[t >> 5] = sum;
    __syncthreads();

    // Final fold: lanes 0-7 each grab 4 contiguous warp sums with one
    // conflict-free LDS.128, pairwise-add, then a 3-deep shfl tree.
    if (t < 8) {
        float4 w = reinterpret_cast<const float4*>(warp_sums)[t];
        float s = (w.x + w.y) + (w.z + w.w);
        #pragma unroll
        for (int off = 4; off > 0; off >>= 1)
            s += __shfl_xor_sync(0x000000FFu, s, off);
        if (t == 0)
            out[9 + b] = s * INV_NEG;
    }
}

extern "C" void kernel_launch(void* const* d_in, const int* in_sizes, int n_in,
                              void* d_out, int out_size) {
    const float* mkpts0 = (const float*)d_in[0];
    float* out = (float*)d_out;
    svdhead_kernel<<<3, TPB>>>(mkpts0, out);
}